// round 1
// baseline (speedup 1.0000x reference)
#include <cuda_runtime.h>
#include <cstdint>
#include <cstddef>

#define B_ 64
#define L_ 512
#define D_ 512
#define F_ 2048
#define E_ 8

// gates[b*E+e], written by gates_kernel, read by both GEMMs
__device__ float g_gates[B_ * E_];
// h scratch: [B*E][L][F] fp32 (only active pairs are written/read)
__device__ float g_h[(size_t)B_ * E_ * L_ * F_];

// ---------------------------------------------------------------------------
// helpers
// ---------------------------------------------------------------------------
__device__ __forceinline__ uint32_t f2tf32(float x) {
    uint32_t r;
    asm("cvt.rna.tf32.f32 %0, %1;" : "=r"(r) : "f"(x));
    return r;
}

__device__ __forceinline__ void mma_tf32(float* d, const uint32_t* a, const uint32_t* b) {
    asm volatile(
        "mma.sync.aligned.m16n8k8.row.col.f32.tf32.tf32.f32 "
        "{%0,%1,%2,%3},{%4,%5,%6,%7},{%8,%9},{%0,%1,%2,%3};\n"
        : "+f"(d[0]), "+f"(d[1]), "+f"(d[2]), "+f"(d[3])
        : "r"(a[0]), "r"(a[1]), "r"(a[2]), "r"(a[3]),
          "r"(b[0]), "r"(b[1]));
}

__device__ __forceinline__ float gelu_exact(float v) {
    return 0.5f * v * (1.0f + erff(v * 0.70710678118654752f));
}

// ---------------------------------------------------------------------------
// Kernel 1: gates (softmax -> mask -> renorm) + guide loss
// ---------------------------------------------------------------------------
__global__ void gates_kernel(const float* __restrict__ logits,
                             const int* __restrict__ masks,
                             float* __restrict__ guide_out) {
    __shared__ float s_m[B_];
    int b = threadIdx.x;  // 64 threads, one per batch row

    float v[E_];
    float mx = -1e30f;
#pragma unroll
    for (int e = 0; e < E_; ++e) {
        v[e] = logits[b * E_ + e];
        mx = fmaxf(mx, v[e]);
    }
    float s = 0.f;
#pragma unroll
    for (int e = 0; e < E_; ++e) {
        v[e] = expf(v[e] - mx);
        s += v[e];
    }
    float inv = 1.0f / s;
    float g[E_];
    float msum = 0.f;
#pragma unroll
    for (int e = 0; e < E_; ++e) {
        float raw = v[e] * inv;
        float m = (masks[b * E_ + e] == 1) ? 1.0f : 0.0f;
        g[e] = raw * m;
        msum += g[e];
    }
    float inv2 = 1.0f / (msum + 1e-9f);
#pragma unroll
    for (int e = 0; e < E_; ++e) g_gates[b * E_ + e] = g[e] * inv2;

    s_m[b] = msum;
    __syncthreads();
    if (b == 0) {
        float t = 0.f;
        for (int i = 0; i < B_; ++i) t += s_m[i];
        float gl = 1.0f - t / (float)B_;
        guide_out[0] = gl * gl;
    }
}

// ---------------------------------------------------------------------------
// Kernel 2: h[b,e] = gelu(x[b] @ w1[e] + b1[e])   (only active pairs)
// block tile 128x128, BK=32, 4 warps each 64x64, m16n8k8 tf32
// grid: (F/128, L/128, B*E)
// ---------------------------------------------------------------------------
__global__ __launch_bounds__(128, 2)
void gemm1_kernel(const float* __restrict__ x,
                  const float* __restrict__ w1,
                  const float* __restrict__ b1) {
    int pair = blockIdx.z;           // b*E + e
    if (g_gates[pair] == 0.0f) return;
    int b = pair >> 3;
    int e = pair & 7;
    int m0 = blockIdx.y * 128;       // over L
    int n0 = blockIdx.x * 128;       // over F

    __shared__ float As[128][36];    // x tile [M][K], pad 4 (16B-aligned rows)
    __shared__ float Bs[32][132];    // w1 tile [K][N], pad 4

    const float* xb  = x  + (size_t)b * L_ * D_;
    const float* w1e = w1 + (size_t)e * D_ * F_;

    int tid  = threadIdx.x;
    int lane = tid & 31;
    int warp = tid >> 5;
    int wm = (warp >> 1) * 64;
    int wn = (warp & 1) * 64;
    int mrow = lane >> 2;            // groupID
    int kcol = lane & 3;             // threadID_in_group

    float acc[4][8][4];
#pragma unroll
    for (int mi = 0; mi < 4; ++mi)
#pragma unroll
        for (int ni = 0; ni < 8; ++ni)
#pragma unroll
            for (int r = 0; r < 4; ++r) acc[mi][ni][r] = 0.f;

    for (int k0 = 0; k0 < D_; k0 += 32) {
        // load A: 128x32 (x rows, k cols)
        {
            int r = tid >> 3, c = (tid & 7) * 4;
#pragma unroll
            for (int i = 0; i < 8; ++i) {
                float4 v = *(const float4*)&xb[(size_t)(m0 + r + i * 16) * D_ + k0 + c];
                *(float4*)&As[r + i * 16][c] = v;
            }
        }
        // load B: 32x128 (w1 rows k, cols n)
        {
            int r = tid >> 5, c = (tid & 31) * 4;
#pragma unroll
            for (int i = 0; i < 8; ++i) {
                *(float4*)&Bs[r + i * 4][c] =
                    *(const float4*)&w1e[(size_t)(k0 + r + i * 4) * F_ + n0 + c];
            }
        }
        __syncthreads();
#pragma unroll
        for (int kk = 0; kk < 32; kk += 8) {
            uint32_t af[4][4], bf[8][2];
#pragma unroll
            for (int mi = 0; mi < 4; ++mi) {
                int r = wm + mi * 16 + mrow;
                af[mi][0] = f2tf32(As[r][kk + kcol]);
                af[mi][1] = f2tf32(As[r + 8][kk + kcol]);
                af[mi][2] = f2tf32(As[r][kk + kcol + 4]);
                af[mi][3] = f2tf32(As[r + 8][kk + kcol + 4]);
            }
#pragma unroll
            for (int ni = 0; ni < 8; ++ni) {
                int c = wn + ni * 8 + mrow;
                bf[ni][0] = f2tf32(Bs[kk + kcol][c]);
                bf[ni][1] = f2tf32(Bs[kk + kcol + 4][c]);
            }
#pragma unroll
            for (int mi = 0; mi < 4; ++mi)
#pragma unroll
                for (int ni = 0; ni < 8; ++ni)
                    mma_tf32(acc[mi][ni], af[mi], bf[ni]);
        }
        __syncthreads();
    }

    // epilogue: gelu(acc + b1) -> g_h
    float* hout = g_h + (size_t)pair * L_ * F_;
    const float* b1e = b1 + e * F_;
#pragma unroll
    for (int mi = 0; mi < 4; ++mi) {
        int r0 = m0 + wm + mi * 16 + mrow;
#pragma unroll
        for (int ni = 0; ni < 8; ++ni) {
            int c0 = n0 + wn + ni * 8 + kcol * 2;
            float bias0 = b1e[c0], bias1 = b1e[c0 + 1];
            hout[(size_t)r0 * F_ + c0]           = gelu_exact(acc[mi][ni][0] + bias0);
            hout[(size_t)r0 * F_ + c0 + 1]       = gelu_exact(acc[mi][ni][1] + bias1);
            hout[(size_t)(r0 + 8) * F_ + c0]     = gelu_exact(acc[mi][ni][2] + bias0);
            hout[(size_t)(r0 + 8) * F_ + c0 + 1] = gelu_exact(acc[mi][ni][3] + bias1);
        }
    }
}

// ---------------------------------------------------------------------------
// Kernel 3: out[b] = sum_e g[b,e] * (h[b,e] @ w2[e]) + sum_e g[b,e]*b2[e]
// gate folded into A-tile load. grid: (D/128, L/128, B)
// ---------------------------------------------------------------------------
__global__ __launch_bounds__(128, 2)
void gemm2_kernel(const float* __restrict__ w2,
                  const float* __restrict__ b2,
                  float* __restrict__ out) {
    int b  = blockIdx.z;
    int m0 = blockIdx.y * 128;       // over L
    int n0 = blockIdx.x * 128;       // over D

    __shared__ float As[128][36];
    __shared__ float Bs[32][132];
    __shared__ float sbias[128];

    int tid  = threadIdx.x;
    int lane = tid & 31;
    int warp = tid >> 5;
    int wm = (warp >> 1) * 64;
    int wn = (warp & 1) * 64;
    int mrow = lane >> 2;
    int kcol = lane & 3;

    // bias column: sum_e g * b2[e, col]
    {
        float bias = 0.f;
#pragma unroll
        for (int e = 0; e < E_; ++e)
            bias += g_gates[b * E_ + e] * b2[e * D_ + n0 + tid];
        sbias[tid] = bias;
    }
    __syncthreads();

    float acc[4][8][4];
#pragma unroll
    for (int mi = 0; mi < 4; ++mi)
#pragma unroll
        for (int ni = 0; ni < 8; ++ni)
#pragma unroll
            for (int r = 0; r < 4; ++r) acc[mi][ni][r] = 0.f;

    for (int e = 0; e < E_; ++e) {
        float g = g_gates[b * E_ + e];
        if (g == 0.0f) continue;     // uniform across block
        const float* hptr = g_h + (size_t)(b * E_ + e) * L_ * F_;
        const float* w2e  = w2 + (size_t)e * F_ * D_;

        for (int k0 = 0; k0 < F_; k0 += 32) {
            // load A: g * h tile 128x32
            {
                int r = tid >> 3, c = (tid & 7) * 4;
#pragma unroll
                for (int i = 0; i < 8; ++i) {
                    float4 v = *(const float4*)&hptr[(size_t)(m0 + r + i * 16) * F_ + k0 + c];
                    v.x *= g; v.y *= g; v.z *= g; v.w *= g;
                    *(float4*)&As[r + i * 16][c] = v;
                }
            }
            // load B: w2 tile 32x128
            {
                int r = tid >> 5, c = (tid & 31) * 4;
#pragma unroll
                for (int i = 0; i < 8; ++i) {
                    *(float4*)&Bs[r + i * 4][c] =
                        *(const float4*)&w2e[(size_t)(k0 + r + i * 4) * D_ + n0 + c];
                }
            }
            __syncthreads();
#pragma unroll
            for (int kk = 0; kk < 32; kk += 8) {
                uint32_t af[4][4], bf[8][2];
#pragma unroll
                for (int mi = 0; mi < 4; ++mi) {
                    int r = wm + mi * 16 + mrow;
                    af[mi][0] = f2tf32(As[r][kk + kcol]);
                    af[mi][1] = f2tf32(As[r + 8][kk + kcol]);
                    af[mi][2] = f2tf32(As[r][kk + kcol + 4]);
                    af[mi][3] = f2tf32(As[r + 8][kk + kcol + 4]);
                }
#pragma unroll
                for (int ni = 0; ni < 8; ++ni) {
                    int c = wn + ni * 8 + mrow;
                    bf[ni][0] = f2tf32(Bs[kk + kcol][c]);
                    bf[ni][1] = f2tf32(Bs[kk + kcol + 4][c]);
                }
#pragma unroll
                for (int mi = 0; mi < 4; ++mi)
#pragma unroll
                    for (int ni = 0; ni < 8; ++ni)
                        mma_tf32(acc[mi][ni], af[mi], bf[ni]);
            }
            __syncthreads();
        }
    }

    // epilogue: out = acc + bias (writes EVERY element; zero-gate rows -> 0)
    float* outb = out + (size_t)b * L_ * D_;
#pragma unroll
    for (int mi = 0; mi < 4; ++mi) {
        int r0 = m0 + wm + mi * 16 + mrow;
#pragma unroll
        for (int ni = 0; ni < 8; ++ni) {
            int cl = wn + ni * 8 + kcol * 2;
            int c0 = n0 + cl;
            float bias0 = sbias[cl], bias1 = sbias[cl + 1];
            outb[(size_t)r0 * D_ + c0]           = acc[mi][ni][0] + bias0;
            outb[(size_t)r0 * D_ + c0 + 1]       = acc[mi][ni][1] + bias1;
            outb[(size_t)(r0 + 8) * D_ + c0]     = acc[mi][ni][2] + bias0;
            outb[(size_t)(r0 + 8) * D_ + c0 + 1] = acc[mi][ni][3] + bias1;
        }
    }
}

// ---------------------------------------------------------------------------
// launch
// ---------------------------------------------------------------------------
extern "C" void kernel_launch(void* const* d_in, const int* in_sizes, int n_in,
                              void* d_out, int out_size) {
    const float* x      = (const float*)d_in[0];
    const float* logits = (const float*)d_in[1];
    const int*   masks  = (const int*)d_in[2];
    const float* w1     = (const float*)d_in[3];
    const float* b1     = (const float*)d_in[4];
    const float* w2     = (const float*)d_in[5];
    const float* b2     = (const float*)d_in[6];
    float* out = (float*)d_out;

    // guide loss goes in the last output element (out is [B,L,D] then scalar)
    gates_kernel<<<1, B_>>>(logits, masks, out + ((size_t)out_size - 1));

    dim3 g1(F_ / 128, L_ / 128, B_ * E_);
    gemm1_kernel<<<g1, 128>>>(x, w1, b1);

    dim3 g2(D_ / 128, L_ / 128, B_);
    gemm2_kernel<<<g2, 128>>>(w2, b2, out);
}

// round 2
// speedup vs baseline: 1.1333x; 1.1333x over previous
#include <cuda_runtime.h>
#include <cstdint>
#include <cstddef>

#define B_ 64
#define L_ 512
#define D_ 512
#define F_ 2048
#define E_ 8

__device__ float g_gates[B_ * E_];
__device__ float g_h[(size_t)B_ * E_ * L_ * F_];

// smem tile geometry (floats)
#define A_STRIDE 36          // 128 rows x 36 (pad 4)
#define B_STRIDE 136         // 32 rows x 136 (pad 8 -> conflict-free B frag loads)
#define A_TILE (128 * A_STRIDE)   // 4608
#define B_TILE (32 * B_STRIDE)    // 4352
#define SMEM_FLOATS (2 * A_TILE + 2 * B_TILE)   // 17920 floats = 71680 B

// ---------------------------------------------------------------------------
// helpers
// ---------------------------------------------------------------------------
__device__ __forceinline__ uint32_t f2tf32(float x) {
    uint32_t r;
    asm("cvt.rna.tf32.f32 %0, %1;" : "=r"(r) : "f"(x));
    return r;
}

__device__ __forceinline__ void mma_tf32(float* d, const uint32_t* a, const uint32_t* b) {
    asm volatile(
        "mma.sync.aligned.m16n8k8.row.col.f32.tf32.tf32.f32 "
        "{%0,%1,%2,%3},{%4,%5,%6,%7},{%8,%9},{%0,%1,%2,%3};\n"
        : "+f"(d[0]), "+f"(d[1]), "+f"(d[2]), "+f"(d[3])
        : "r"(a[0]), "r"(a[1]), "r"(a[2]), "r"(a[3]),
          "r"(b[0]), "r"(b[1]));
}

__device__ __forceinline__ void cp16(void* smem_dst, const void* gsrc) {
    uint32_t s = (uint32_t)__cvta_generic_to_shared(smem_dst);
    asm volatile("cp.async.cg.shared.global [%0], [%1], 16;" :: "r"(s), "l"(gsrc));
}
#define CP_COMMIT() asm volatile("cp.async.commit_group;")
#define CP_WAIT1()  asm volatile("cp.async.wait_group 1;")
#define CP_WAIT0()  asm volatile("cp.async.wait_group 0;")

__device__ __forceinline__ float gelu_exact(float v) {
    return 0.5f * v * (1.0f + erff(v * 0.70710678118654752f));
}

// ---------------------------------------------------------------------------
// Kernel 1: gates + guide loss
// ---------------------------------------------------------------------------
__global__ void gates_kernel(const float* __restrict__ logits,
                             const int* __restrict__ masks,
                             float* __restrict__ guide_out) {
    __shared__ float s_m[B_];
    int b = threadIdx.x;

    float v[E_];
    float mx = -1e30f;
#pragma unroll
    for (int e = 0; e < E_; ++e) {
        v[e] = logits[b * E_ + e];
        mx = fmaxf(mx, v[e]);
    }
    float s = 0.f;
#pragma unroll
    for (int e = 0; e < E_; ++e) { v[e] = expf(v[e] - mx); s += v[e]; }
    float inv = 1.0f / s;
    float g[E_];
    float msum = 0.f;
#pragma unroll
    for (int e = 0; e < E_; ++e) {
        float raw = v[e] * inv;
        float m = (masks[b * E_ + e] == 1) ? 1.0f : 0.0f;
        g[e] = raw * m;
        msum += g[e];
    }
    float inv2 = 1.0f / (msum + 1e-9f);
#pragma unroll
    for (int e = 0; e < E_; ++e) g_gates[b * E_ + e] = g[e] * inv2;

    s_m[b] = msum;
    __syncthreads();
    if (b == 0) {
        float t = 0.f;
        for (int i = 0; i < B_; ++i) t += s_m[i];
        float gl = 1.0f - t / (float)B_;
        guide_out[0] = gl * gl;
    }
}

// ---------------------------------------------------------------------------
// Kernel 2: h[b,e] = gelu(x[b] @ w1[e] + b1[e])  — 2-stage cp.async pipeline
// ---------------------------------------------------------------------------
__global__ __launch_bounds__(128, 2)
void gemm1_kernel(const float* __restrict__ x,
                  const float* __restrict__ w1,
                  const float* __restrict__ b1) {
    int pair = blockIdx.z;
    if (g_gates[pair] == 0.0f) return;
    int b = pair >> 3;
    int e = pair & 7;
    int m0 = blockIdx.y * 128;
    int n0 = blockIdx.x * 128;

    extern __shared__ float sm[];
    float* As = sm;                   // [2][128][A_STRIDE]
    float* Bs = sm + 2 * A_TILE;      // [2][32][B_STRIDE]

    const float* xb  = x  + (size_t)b * L_ * D_;
    const float* w1e = w1 + (size_t)e * D_ * F_;

    int tid  = threadIdx.x;
    int lane = tid & 31;
    int warp = tid >> 5;
    int wm = (warp >> 1) * 64;
    int wn = (warp & 1) * 64;
    int mrow = lane >> 2;
    int kcol = lane & 3;

    int ar = tid >> 3, ac = (tid & 7) * 4;     // A loader coords
    int br = tid >> 5, bc = (tid & 31) * 4;    // B loader coords

    float acc[4][8][4];
#pragma unroll
    for (int mi = 0; mi < 4; ++mi)
#pragma unroll
        for (int ni = 0; ni < 8; ++ni)
#pragma unroll
            for (int r = 0; r < 4; ++r) acc[mi][ni][r] = 0.f;

    auto load_stage = [&](int s, int k0) {
        float* Ad = As + s * A_TILE;
        float* Bd = Bs + s * B_TILE;
#pragma unroll
        for (int i = 0; i < 8; ++i)
            cp16(&Ad[(ar + i * 16) * A_STRIDE + ac],
                 &xb[(size_t)(m0 + ar + i * 16) * D_ + k0 + ac]);
#pragma unroll
        for (int i = 0; i < 8; ++i)
            cp16(&Bd[(br + i * 4) * B_STRIDE + bc],
                 &w1e[(size_t)(k0 + br + i * 4) * F_ + n0 + bc]);
        CP_COMMIT();
    };

    load_stage(0, 0);
    int st = 0;
    for (int k0 = 0; k0 < D_; k0 += 32) {
        bool more = (k0 + 32 < D_);
        if (more) load_stage(st ^ 1, k0 + 32);
        if (more) CP_WAIT1(); else CP_WAIT0();
        __syncthreads();

        const float* Ac = As + st * A_TILE;
        const float* Bc = Bs + st * B_TILE;
#pragma unroll
        for (int kk = 0; kk < 32; kk += 8) {
            uint32_t af[4][4], bf[8][2];
#pragma unroll
            for (int mi = 0; mi < 4; ++mi) {
                int r = wm + mi * 16 + mrow;
                af[mi][0] = f2tf32(Ac[r * A_STRIDE + kk + kcol]);
                af[mi][1] = f2tf32(Ac[(r + 8) * A_STRIDE + kk + kcol]);
                af[mi][2] = f2tf32(Ac[r * A_STRIDE + kk + kcol + 4]);
                af[mi][3] = f2tf32(Ac[(r + 8) * A_STRIDE + kk + kcol + 4]);
            }
#pragma unroll
            for (int ni = 0; ni < 8; ++ni) {
                int c = wn + ni * 8 + mrow;
                bf[ni][0] = f2tf32(Bc[(kk + kcol) * B_STRIDE + c]);
                bf[ni][1] = f2tf32(Bc[(kk + kcol + 4) * B_STRIDE + c]);
            }
#pragma unroll
            for (int mi = 0; mi < 4; ++mi)
#pragma unroll
                for (int ni = 0; ni < 8; ++ni)
                    mma_tf32(acc[mi][ni], af[mi], bf[ni]);
        }
        __syncthreads();
        st ^= 1;
    }

    float* hout = g_h + (size_t)pair * L_ * F_;
    const float* b1e = b1 + e * F_;
#pragma unroll
    for (int mi = 0; mi < 4; ++mi) {
        int r0 = m0 + wm + mi * 16 + mrow;
#pragma unroll
        for (int ni = 0; ni < 8; ++ni) {
            int c0 = n0 + wn + ni * 8 + kcol * 2;
            float bias0 = b1e[c0], bias1 = b1e[c0 + 1];
            hout[(size_t)r0 * F_ + c0]           = gelu_exact(acc[mi][ni][0] + bias0);
            hout[(size_t)r0 * F_ + c0 + 1]       = gelu_exact(acc[mi][ni][1] + bias1);
            hout[(size_t)(r0 + 8) * F_ + c0]     = gelu_exact(acc[mi][ni][2] + bias0);
            hout[(size_t)(r0 + 8) * F_ + c0 + 1] = gelu_exact(acc[mi][ni][3] + bias1);
        }
    }
}

// ---------------------------------------------------------------------------
// Kernel 3: out[b] = sum_e g*(h[b,e] @ w2[e]) + sum_e g*b2[e]
// flattened (expert, k) pipelined loop; gate folded into A-frag cvt
// ---------------------------------------------------------------------------
__global__ __launch_bounds__(128, 2)
void gemm2_kernel(const float* __restrict__ w2,
                  const float* __restrict__ b2,
                  float* __restrict__ out) {
    int b  = blockIdx.z;
    int m0 = blockIdx.y * 128;
    int n0 = blockIdx.x * 128;

    extern __shared__ float sm[];
    float* As = sm;
    float* Bs = sm + 2 * A_TILE;
    __shared__ float sbias[128];

    int tid  = threadIdx.x;
    int lane = tid & 31;
    int warp = tid >> 5;
    int wm = (warp >> 1) * 64;
    int wn = (warp & 1) * 64;
    int mrow = lane >> 2;
    int kcol = lane & 3;

    int ar = tid >> 3, ac = (tid & 7) * 4;
    int br = tid >> 5, bc = (tid & 31) * 4;

    // active expert list (uniform across block)
    int act[E_]; float gact[E_]; int nact = 0;
#pragma unroll
    for (int e = 0; e < E_; ++e) {
        float g = g_gates[b * E_ + e];
        if (g != 0.0f) { act[nact] = e; gact[nact] = g; ++nact; }
    }

    // bias: sum_e g * b2[e, col]
    {
        float bias = 0.f;
        for (int i = 0; i < nact; ++i)
            bias += gact[i] * b2[act[i] * D_ + n0 + tid];
        sbias[tid] = bias;
    }
    __syncthreads();

    float acc[4][8][4];
#pragma unroll
    for (int mi = 0; mi < 4; ++mi)
#pragma unroll
        for (int ni = 0; ni < 8; ++ni)
#pragma unroll
            for (int r = 0; r < 4; ++r) acc[mi][ni][r] = 0.f;

    const int KITERS = F_ / 32;               // 64
    int total = nact * KITERS;

    auto load_stage = [&](int s, int t) {
        int ei = t >> 6;                      // t / KITERS
        int k0 = (t & 63) << 5;               // (t % KITERS) * 32
        const float* hptr = g_h + (size_t)(b * E_ + act[ei]) * L_ * F_;
        const float* w2e  = w2 + (size_t)act[ei] * F_ * D_;
        float* Ad = As + s * A_TILE;
        float* Bd = Bs + s * B_TILE;
#pragma unroll
        for (int i = 0; i < 8; ++i)
            cp16(&Ad[(ar + i * 16) * A_STRIDE + ac],
                 &hptr[(size_t)(m0 + ar + i * 16) * F_ + k0 + ac]);
#pragma unroll
        for (int i = 0; i < 8; ++i)
            cp16(&Bd[(br + i * 4) * B_STRIDE + bc],
                 &w2e[(size_t)(k0 + br + i * 4) * D_ + n0 + bc]);
        CP_COMMIT();
    };

    if (total > 0) {
        load_stage(0, 0);
        int st = 0;
        for (int t = 0; t < total; ++t) {
            bool more = (t + 1 < total);
            if (more) load_stage(st ^ 1, t + 1);
            if (more) CP_WAIT1(); else CP_WAIT0();
            __syncthreads();

            float g = gact[t >> 6];
            const float* Ac = As + st * A_TILE;
            const float* Bc = Bs + st * B_TILE;
#pragma unroll
            for (int kk = 0; kk < 32; kk += 8) {
                uint32_t af[4][4], bf[8][2];
#pragma unroll
                for (int mi = 0; mi < 4; ++mi) {
                    int r = wm + mi * 16 + mrow;
                    af[mi][0] = f2tf32(g * Ac[r * A_STRIDE + kk + kcol]);
                    af[mi][1] = f2tf32(g * Ac[(r + 8) * A_STRIDE + kk + kcol]);
                    af[mi][2] = f2tf32(g * Ac[r * A_STRIDE + kk + kcol + 4]);
                    af[mi][3] = f2tf32(g * Ac[(r + 8) * A_STRIDE + kk + kcol + 4]);
                }
#pragma unroll
                for (int ni = 0; ni < 8; ++ni) {
                    int c = wn + ni * 8 + mrow;
                    bf[ni][0] = f2tf32(Bc[(kk + kcol) * B_STRIDE + c]);
                    bf[ni][1] = f2tf32(Bc[(kk + kcol + 4) * B_STRIDE + c]);
                }
#pragma unroll
                for (int mi = 0; mi < 4; ++mi)
#pragma unroll
                    for (int ni = 0; ni < 8; ++ni)
                        mma_tf32(acc[mi][ni], af[mi], bf[ni]);
            }
            __syncthreads();
            st ^= 1;
        }
    }

    float* outb = out + (size_t)b * L_ * D_;
#pragma unroll
    for (int mi = 0; mi < 4; ++mi) {
        int r0 = m0 + wm + mi * 16 + mrow;
#pragma unroll
        for (int ni = 0; ni < 8; ++ni) {
            int cl = wn + ni * 8 + kcol * 2;
            int c0 = n0 + cl;
            float bias0 = sbias[cl], bias1 = sbias[cl + 1];
            outb[(size_t)r0 * D_ + c0]           = acc[mi][ni][0] + bias0;
            outb[(size_t)r0 * D_ + c0 + 1]       = acc[mi][ni][1] + bias1;
            outb[(size_t)(r0 + 8) * D_ + c0]     = acc[mi][ni][2] + bias0;
            outb[(size_t)(r0 + 8) * D_ + c0 + 1] = acc[mi][ni][3] + bias1;
        }
    }
}

// ---------------------------------------------------------------------------
// launch
// ---------------------------------------------------------------------------
extern "C" void kernel_launch(void* const* d_in, const int* in_sizes, int n_in,
                              void* d_out, int out_size) {
    const float* x      = (const float*)d_in[0];
    const float* logits = (const float*)d_in[1];
    const int*   masks  = (const int*)d_in[2];
    const float* w1     = (const float*)d_in[3];
    const float* b1     = (const float*)d_in[4];
    const float* w2     = (const float*)d_in[5];
    const float* b2     = (const float*)d_in[6];
    float* out = (float*)d_out;

    static bool attr_done = false;
    if (!attr_done) {
        cudaFuncSetAttribute(gemm1_kernel, cudaFuncAttributeMaxDynamicSharedMemorySize,
                             SMEM_FLOATS * sizeof(float));
        cudaFuncSetAttribute(gemm2_kernel, cudaFuncAttributeMaxDynamicSharedMemorySize,
                             SMEM_FLOATS * sizeof(float));
        attr_done = true;
    }

    gates_kernel<<<1, B_>>>(logits, masks, out + ((size_t)out_size - 1));

    dim3 g1(F_ / 128, L_ / 128, B_ * E_);
    gemm1_kernel<<<g1, 128, SMEM_FLOATS * sizeof(float)>>>(x, w1, b1);

    dim3 g2(D_ / 128, L_ / 128, B_);
    gemm2_kernel<<<g2, 128, SMEM_FLOATS * sizeof(float)>>>(w2, b2, out);
}

// round 3
// speedup vs baseline: 1.2644x; 1.1156x over previous
#include <cuda_runtime.h>
#include <cstdint>
#include <cstddef>

#define B_ 64
#define L_ 512
#define D_ 512
#define F_ 2048
#define E_ 8

__device__ float g_gates[B_ * E_];
__device__ float g_h[(size_t)B_ * E_ * L_ * F_];
// tf32-pre-rounded copies (rounded once per call, used many times)
__device__ float g_xr[(size_t)B_ * L_ * D_];
__device__ float g_w1r[(size_t)E_ * D_ * F_];
__device__ float g_w2r[(size_t)E_ * F_ * D_];

// smem tile geometry (floats)
#define A_STRIDE 36
#define B_STRIDE 136
#define A_TILE (128 * A_STRIDE)
#define B_TILE (32 * B_STRIDE)
#define SMEM_FLOATS (2 * A_TILE + 2 * B_TILE)   // 71680 B

// ---------------------------------------------------------------------------
// helpers
// ---------------------------------------------------------------------------
__device__ __forceinline__ uint32_t f2tf32(float x) {
    uint32_t r;
    asm("cvt.rna.tf32.f32 %0, %1;" : "=r"(r) : "f"(x));
    return r;
}

__device__ __forceinline__ void mma_tf32(float* d, const uint32_t* a, const uint32_t* b) {
    asm volatile(
        "mma.sync.aligned.m16n8k8.row.col.f32.tf32.tf32.f32 "
        "{%0,%1,%2,%3},{%4,%5,%6,%7},{%8,%9},{%0,%1,%2,%3};\n"
        : "+f"(d[0]), "+f"(d[1]), "+f"(d[2]), "+f"(d[3])
        : "r"(a[0]), "r"(a[1]), "r"(a[2]), "r"(a[3]),
          "r"(b[0]), "r"(b[1]));
}

__device__ __forceinline__ void cp16(void* smem_dst, const void* gsrc) {
    uint32_t s = (uint32_t)__cvta_generic_to_shared(smem_dst);
    asm volatile("cp.async.cg.shared.global [%0], [%1], 16;" :: "r"(s), "l"(gsrc));
}
#define CP_COMMIT() asm volatile("cp.async.commit_group;")
#define CP_WAIT1()  asm volatile("cp.async.wait_group 1;")
#define CP_WAIT0()  asm volatile("cp.async.wait_group 0;")

__device__ __forceinline__ float gelu_exact(float v) {
    return 0.5f * v * (1.0f + erff(v * 0.70710678118654752f));
}

// ---------------------------------------------------------------------------
// Kernel 0: pre-round x, w1, w2 to tf32 bit patterns (RNA), stored as fp32
// ---------------------------------------------------------------------------
__global__ void preround_kernel(const float* __restrict__ x,
                                const float* __restrict__ w1,
                                const float* __restrict__ w2) {
    size_t i = (size_t)blockIdx.x * blockDim.x + threadIdx.x;
    size_t stride = (size_t)gridDim.x * blockDim.x;
    const size_t NX = (size_t)B_ * L_ * D_;
    const size_t NW = (size_t)E_ * D_ * F_;
    for (size_t j = i; j < NX; j += stride)
        g_xr[j] = __uint_as_float(f2tf32(x[j]));
    for (size_t j = i; j < NW; j += stride) {
        g_w1r[j] = __uint_as_float(f2tf32(w1[j]));
        g_w2r[j] = __uint_as_float(f2tf32(w2[j]));
    }
}

// ---------------------------------------------------------------------------
// Kernel 1: gates + guide loss
// ---------------------------------------------------------------------------
__global__ void gates_kernel(const float* __restrict__ logits,
                             const int* __restrict__ masks,
                             float* __restrict__ guide_out) {
    __shared__ float s_m[B_];
    int b = threadIdx.x;

    float v[E_];
    float mx = -1e30f;
#pragma unroll
    for (int e = 0; e < E_; ++e) {
        v[e] = logits[b * E_ + e];
        mx = fmaxf(mx, v[e]);
    }
    float s = 0.f;
#pragma unroll
    for (int e = 0; e < E_; ++e) { v[e] = expf(v[e] - mx); s += v[e]; }
    float inv = 1.0f / s;
    float g[E_];
    float msum = 0.f;
#pragma unroll
    for (int e = 0; e < E_; ++e) {
        float raw = v[e] * inv;
        float m = (masks[b * E_ + e] == 1) ? 1.0f : 0.0f;
        g[e] = raw * m;
        msum += g[e];
    }
    float inv2 = 1.0f / (msum + 1e-9f);
#pragma unroll
    for (int e = 0; e < E_; ++e) g_gates[b * E_ + e] = g[e] * inv2;

    s_m[b] = msum;
    __syncthreads();
    if (b == 0) {
        float t = 0.f;
        for (int i = 0; i < B_; ++i) t += s_m[i];
        float gl = 1.0f - t / (float)B_;
        guide_out[0] = gl * gl;
    }
}

// ---------------------------------------------------------------------------
// Kernel 2: h[b,e] = tf32round(gelu(x[b] @ w1[e] + b1[e]))   (active pairs)
// no cvt in mainloop — operands pre-rounded
// ---------------------------------------------------------------------------
__global__ __launch_bounds__(128, 2)
void gemm1_kernel(const float* __restrict__ b1) {
    int pair = blockIdx.z;
    if (g_gates[pair] == 0.0f) return;
    int b = pair >> 3;
    int e = pair & 7;
    int m0 = blockIdx.y * 128;
    int n0 = blockIdx.x * 128;

    extern __shared__ float sm[];
    float* As = sm;
    float* Bs = sm + 2 * A_TILE;

    const float* xb  = g_xr  + (size_t)b * L_ * D_;
    const float* w1e = g_w1r + (size_t)e * D_ * F_;

    int tid  = threadIdx.x;
    int lane = tid & 31;
    int warp = tid >> 5;
    int wm = (warp >> 1) * 64;
    int wn = (warp & 1) * 64;
    int mrow = lane >> 2;
    int kcol = lane & 3;

    int ar = tid >> 3, ac = (tid & 7) * 4;
    int br = tid >> 5, bc = (tid & 31) * 4;

    float acc[4][8][4];
#pragma unroll
    for (int mi = 0; mi < 4; ++mi)
#pragma unroll
        for (int ni = 0; ni < 8; ++ni)
#pragma unroll
            for (int r = 0; r < 4; ++r) acc[mi][ni][r] = 0.f;

    auto load_stage = [&](int s, int k0) {
        float* Ad = As + s * A_TILE;
        float* Bd = Bs + s * B_TILE;
#pragma unroll
        for (int i = 0; i < 8; ++i)
            cp16(&Ad[(ar + i * 16) * A_STRIDE + ac],
                 &xb[(size_t)(m0 + ar + i * 16) * D_ + k0 + ac]);
#pragma unroll
        for (int i = 0; i < 8; ++i)
            cp16(&Bd[(br + i * 4) * B_STRIDE + bc],
                 &w1e[(size_t)(k0 + br + i * 4) * F_ + n0 + bc]);
        CP_COMMIT();
    };

    load_stage(0, 0);
    int st = 0;
    for (int k0 = 0; k0 < D_; k0 += 32) {
        bool more = (k0 + 32 < D_);
        if (more) load_stage(st ^ 1, k0 + 32);
        if (more) CP_WAIT1(); else CP_WAIT0();
        __syncthreads();

        const float* Ac = As + st * A_TILE;
        const float* Bc = Bs + st * B_TILE;
#pragma unroll
        for (int kk = 0; kk < 32; kk += 8) {
            uint32_t af[4][4], bf[8][2];
#pragma unroll
            for (int mi = 0; mi < 4; ++mi) {
                int r = wm + mi * 16 + mrow;
                af[mi][0] = __float_as_uint(Ac[r * A_STRIDE + kk + kcol]);
                af[mi][1] = __float_as_uint(Ac[(r + 8) * A_STRIDE + kk + kcol]);
                af[mi][2] = __float_as_uint(Ac[r * A_STRIDE + kk + kcol + 4]);
                af[mi][3] = __float_as_uint(Ac[(r + 8) * A_STRIDE + kk + kcol + 4]);
            }
#pragma unroll
            for (int ni = 0; ni < 8; ++ni) {
                int c = wn + ni * 8 + mrow;
                bf[ni][0] = __float_as_uint(Bc[(kk + kcol) * B_STRIDE + c]);
                bf[ni][1] = __float_as_uint(Bc[(kk + kcol + 4) * B_STRIDE + c]);
            }
#pragma unroll
            for (int mi = 0; mi < 4; ++mi)
#pragma unroll
                for (int ni = 0; ni < 8; ++ni)
                    mma_tf32(acc[mi][ni], af[mi], bf[ni]);
        }
        __syncthreads();
        st ^= 1;
    }

    // epilogue: tf32round(gelu(acc + b1)) -> g_h (so GEMM2 needs no cvt)
    float* hout = g_h + (size_t)pair * L_ * F_;
    const float* b1e = b1 + e * F_;
#pragma unroll
    for (int mi = 0; mi < 4; ++mi) {
        int r0 = m0 + wm + mi * 16 + mrow;
#pragma unroll
        for (int ni = 0; ni < 8; ++ni) {
            int c0 = n0 + wn + ni * 8 + kcol * 2;
            float bias0 = b1e[c0], bias1 = b1e[c0 + 1];
            hout[(size_t)r0 * F_ + c0]           = __uint_as_float(f2tf32(gelu_exact(acc[mi][ni][0] + bias0)));
            hout[(size_t)r0 * F_ + c0 + 1]       = __uint_as_float(f2tf32(gelu_exact(acc[mi][ni][1] + bias1)));
            hout[(size_t)(r0 + 8) * F_ + c0]     = __uint_as_float(f2tf32(gelu_exact(acc[mi][ni][2] + bias0)));
            hout[(size_t)(r0 + 8) * F_ + c0 + 1] = __uint_as_float(f2tf32(gelu_exact(acc[mi][ni][3] + bias1)));
        }
    }
}

// ---------------------------------------------------------------------------
// Kernel 3: out[b] = sum_e g*(h[b,e] @ w2[e]) + sum_e g*b2[e]
// gate applied via accumulator rescale at expert boundaries (exact telescoping)
// ---------------------------------------------------------------------------
__global__ __launch_bounds__(128, 2)
void gemm2_kernel(const float* __restrict__ b2,
                  float* __restrict__ out) {
    int b  = blockIdx.z;
    int m0 = blockIdx.y * 128;
    int n0 = blockIdx.x * 128;

    extern __shared__ float sm[];
    float* As = sm;
    float* Bs = sm + 2 * A_TILE;
    __shared__ float sbias[128];

    int tid  = threadIdx.x;
    int lane = tid & 31;
    int warp = tid >> 5;
    int wm = (warp >> 1) * 64;
    int wn = (warp & 1) * 64;
    int mrow = lane >> 2;
    int kcol = lane & 3;

    int ar = tid >> 3, ac = (tid & 7) * 4;
    int br = tid >> 5, bc = (tid & 31) * 4;

    int act[E_]; float gact[E_]; int nact = 0;
#pragma unroll
    for (int e = 0; e < E_; ++e) {
        float g = g_gates[b * E_ + e];
        if (g != 0.0f) { act[nact] = e; gact[nact] = g; ++nact; }
    }

    {
        float bias = 0.f;
        for (int i = 0; i < nact; ++i)
            bias += gact[i] * b2[act[i] * D_ + n0 + tid];
        sbias[tid] = bias;
    }
    __syncthreads();

    float acc[4][8][4];
#pragma unroll
    for (int mi = 0; mi < 4; ++mi)
#pragma unroll
        for (int ni = 0; ni < 8; ++ni)
#pragma unroll
            for (int r = 0; r < 4; ++r) acc[mi][ni][r] = 0.f;

    const int KITERS = F_ / 32;               // 64
    int total = nact * KITERS;

    auto load_stage = [&](int s, int t) {
        int ei = t >> 6;
        int k0 = (t & 63) << 5;
        const float* hptr = g_h + (size_t)(b * E_ + act[ei]) * L_ * F_;
        const float* w2e  = g_w2r + (size_t)act[ei] * F_ * D_;
        float* Ad = As + s * A_TILE;
        float* Bd = Bs + s * B_TILE;
#pragma unroll
        for (int i = 0; i < 8; ++i)
            cp16(&Ad[(ar + i * 16) * A_STRIDE + ac],
                 &hptr[(size_t)(m0 + ar + i * 16) * F_ + k0 + ac]);
#pragma unroll
        for (int i = 0; i < 8; ++i)
            cp16(&Bd[(br + i * 4) * B_STRIDE + bc],
                 &w2e[(size_t)(k0 + br + i * 4) * D_ + n0 + bc]);
        CP_COMMIT();
    };

    if (total > 0) {
        load_stage(0, 0);
        int st = 0;
        for (int t = 0; t < total; ++t) {
            bool more = (t + 1 < total);
            if (more) load_stage(st ^ 1, t + 1);
            if (more) CP_WAIT1(); else CP_WAIT0();
            __syncthreads();

            // expert boundary: rescale accumulator so each expert's partial
            // ends up weighted by its own gate (telescoping product)
            if ((t & 63) == 0 && t > 0) {
                int ei = t >> 6;
                float ratio = gact[ei - 1] / gact[ei];
#pragma unroll
                for (int mi = 0; mi < 4; ++mi)
#pragma unroll
                    for (int ni = 0; ni < 8; ++ni)
#pragma unroll
                        for (int r = 0; r < 4; ++r) acc[mi][ni][r] *= ratio;
            }

            const float* Ac = As + st * A_TILE;
            const float* Bc = Bs + st * B_TILE;
#pragma unroll
            for (int kk = 0; kk < 32; kk += 8) {
                uint32_t af[4][4], bf[8][2];
#pragma unroll
                for (int mi = 0; mi < 4; ++mi) {
                    int r = wm + mi * 16 + mrow;
                    af[mi][0] = __float_as_uint(Ac[r * A_STRIDE + kk + kcol]);
                    af[mi][1] = __float_as_uint(Ac[(r + 8) * A_STRIDE + kk + kcol]);
                    af[mi][2] = __float_as_uint(Ac[r * A_STRIDE + kk + kcol + 4]);
                    af[mi][3] = __float_as_uint(Ac[(r + 8) * A_STRIDE + kk + kcol + 4]);
                }
#pragma unroll
                for (int ni = 0; ni < 8; ++ni) {
                    int c = wn + ni * 8 + mrow;
                    bf[ni][0] = __float_as_uint(Bc[(kk + kcol) * B_STRIDE + c]);
                    bf[ni][1] = __float_as_uint(Bc[(kk + kcol + 4) * B_STRIDE + c]);
                }
#pragma unroll
                for (int mi = 0; mi < 4; ++mi)
#pragma unroll
                    for (int ni = 0; ni < 8; ++ni)
                        mma_tf32(acc[mi][ni], af[mi], bf[ni]);
            }
            __syncthreads();
            st ^= 1;
        }
        // final gate scale for the last expert
        float glast = gact[nact - 1];
#pragma unroll
        for (int mi = 0; mi < 4; ++mi)
#pragma unroll
            for (int ni = 0; ni < 8; ++ni)
#pragma unroll
                for (int r = 0; r < 4; ++r) acc[mi][ni][r] *= glast;
    }

    float* outb = out + (size_t)b * L_ * D_;
#pragma unroll
    for (int mi = 0; mi < 4; ++mi) {
        int r0 = m0 + wm + mi * 16 + mrow;
#pragma unroll
        for (int ni = 0; ni < 8; ++ni) {
            int cl = wn + ni * 8 + kcol * 2;
            int c0 = n0 + cl;
            float bias0 = sbias[cl], bias1 = sbias[cl + 1];
            outb[(size_t)r0 * D_ + c0]           = acc[mi][ni][0] + bias0;
            outb[(size_t)r0 * D_ + c0 + 1]       = acc[mi][ni][1] + bias1;
            outb[(size_t)(r0 + 8) * D_ + c0]     = acc[mi][ni][2] + bias0;
            outb[(size_t)(r0 + 8) * D_ + c0 + 1] = acc[mi][ni][3] + bias1;
        }
    }
}

// ---------------------------------------------------------------------------
// launch
// ---------------------------------------------------------------------------
extern "C" void kernel_launch(void* const* d_in, const int* in_sizes, int n_in,
                              void* d_out, int out_size) {
    const float* x      = (const float*)d_in[0];
    const float* logits = (const float*)d_in[1];
    const int*   masks  = (const int*)d_in[2];
    const float* w1     = (const float*)d_in[3];
    const float* b1     = (const float*)d_in[4];
    const float* w2     = (const float*)d_in[5];
    const float* b2     = (const float*)d_in[6];
    float* out = (float*)d_out;

    static bool attr_done = false;
    if (!attr_done) {
        cudaFuncSetAttribute(gemm1_kernel, cudaFuncAttributeMaxDynamicSharedMemorySize,
                             SMEM_FLOATS * sizeof(float));
        cudaFuncSetAttribute(gemm2_kernel, cudaFuncAttributeMaxDynamicSharedMemorySize,
                             SMEM_FLOATS * sizeof(float));
        attr_done = true;
    }

    preround_kernel<<<1024, 256>>>(x, w1, w2);
    gates_kernel<<<1, B_>>>(logits, masks, out + ((size_t)out_size - 1));

    dim3 g1(F_ / 128, L_ / 128, B_ * E_);
    gemm1_kernel<<<g1, 128, SMEM_FLOATS * sizeof(float)>>>(b1);

    dim3 g2(D_ / 128, L_ / 128, B_);
    gemm2_kernel<<<g2, 128, SMEM_FLOATS * sizeof(float)>>>(b2, out);
}